// round 1
// baseline (speedup 1.0000x reference)
#include <cuda_runtime.h>
#include <math.h>

// Problem constants
#define Bb   4
#define Ll   1024
#define Dd   1280
#define Hh   20
#define HD   64
#define BH   (Bb*Hh)        // 80
#define LKV  (2*Ll)         // 2048
#define Mm   (Bb*Ll)        // 4096
#define ALPHA 0.48f
#define SMSCALE 0.125f      // 1/sqrt(64)

// Persistent scratch (device globals; no allocation allowed)
__device__ float g_Q[BH * Ll * HD];          // [bh][q][d]
__device__ float g_K[BH * LKV * HD];         // [bh][kv][d]
__device__ float g_V[BH * LKV * HD];         // [bh][kv][d]
__device__ float g_Ctx[Mm * Dd];             // [b*L + l][h*64 + d]  (standard row-major)

// ---------------------------------------------------------------------------
// 1) Scale-copy the context-bank KV into the back half of g_K / g_V
// ---------------------------------------------------------------------------
__global__ void bg_copy_kernel(const float4* __restrict__ Kbg,
                               const float4* __restrict__ Vbg) {
    int i = blockIdx.x * blockDim.x + threadIdx.x;   // over 80*1024*16 float4
    const int NBG4 = BH * Ll * (HD / 4);             // 1,310,720
    if (i >= NBG4) return;
    int bh  = i >> 14;            // / (1024*16)
    int rem = i & 16383;          // l*16 + d4
    int dst = bh * (LKV * HD / 4) + (Ll * HD / 4) + rem;
    float4 k = Kbg[i];
    float4 v = Vbg[i];
    k.x *= ALPHA; k.y *= ALPHA; k.z *= ALPHA; k.w *= ALPHA;
    v.x *= ALPHA; v.y *= ALPHA; v.z *= ALPHA; v.w *= ALPHA;
    ((float4*)g_K)[dst] = k;
    ((float4*)g_V)[dst] = v;
}

// ---------------------------------------------------------------------------
// 2) QKV projection GEMM: C[4096,1280] = X @ W{q,k,v}, scatter to head layout
//    BM=BN=64, BK=16, 256 threads, 4x4 per thread
// ---------------------------------------------------------------------------
__global__ void proj_kernel(const float* __restrict__ X,
                            const float* __restrict__ Wq,
                            const float* __restrict__ Wk,
                            const float* __restrict__ Wv) {
    __shared__ float As[16][68];   // [k][m] transposed, padded
    __shared__ float Bs[16][64];   // [k][n]

    const int m0 = blockIdx.y * 64;
    const int n0 = blockIdx.x * 64;
    const int z  = blockIdx.z;
    const float* __restrict__ W = (z == 0) ? Wq : ((z == 1) ? Wk : Wv);

    const int t  = threadIdx.x;
    const int tx = t & 15, ty = t >> 4;
    const int ar = t >> 2, ac = t & 3;     // A loader: row, float4-col
    const int br = t >> 4, bc = t & 15;    // B loader: row, float4-col

    float acc[4][4] = {};
    const float* Xp = X + (m0 + ar) * Dd + ac * 4;

    for (int k0 = 0; k0 < Dd; k0 += 16) {
        float4 xa = *(const float4*)(Xp + k0);
        float4 wb = *(const float4*)(W + (k0 + br) * Dd + n0 + bc * 4);
        __syncthreads();
        As[ac*4+0][ar] = xa.x; As[ac*4+1][ar] = xa.y;
        As[ac*4+2][ar] = xa.z; As[ac*4+3][ar] = xa.w;
        *(float4*)&Bs[br][bc*4] = wb;
        __syncthreads();
#pragma unroll
        for (int k = 0; k < 16; k++) {
            float4 a4 = *(const float4*)&As[k][ty*4];
            float4 b4 = *(const float4*)&Bs[k][tx*4];
            float av[4] = {a4.x, a4.y, a4.z, a4.w};
            float bv[4] = {b4.x, b4.y, b4.z, b4.w};
#pragma unroll
            for (int i = 0; i < 4; i++)
#pragma unroll
                for (int j = 0; j < 4; j++)
                    acc[i][j] = fmaf(av[i], bv[j], acc[i][j]);
        }
    }

    // Epilogue: scatter into head-batched layout. n-tile is head-aligned.
    const int h = n0 >> 6;   // head index (64-wide tiles align with heads)
    const int d = tx * 4;
#pragma unroll
    for (int i = 0; i < 4; i++) {
        int m = m0 + ty * 4 + i;
        int b = m >> 10, l = m & 1023;
        float4 v = make_float4(acc[i][0], acc[i][1], acc[i][2], acc[i][3]);
        if (z == 0) {
            *(float4*)&g_Q[((b * Hh + h) * Ll + l) * HD + d] = v;
        } else if (z == 1) {
            *(float4*)&g_K[((b * Hh + h) * LKV + l) * HD + d] = v;
        } else {
            *(float4*)&g_V[((b * Hh + h) * LKV + l) * HD + d] = v;
        }
    }
}

// ---------------------------------------------------------------------------
// 3) Flash attention: one block = (head bh, 64-query tile). 256 threads.
// ---------------------------------------------------------------------------
__device__ __forceinline__ void load_tile_T(float (*dst)[64], const float* __restrict__ g,
                                            float scale) {
    // global [row][64] -> smem [d][row], scaled
    int t = threadIdx.x;
    int r = t >> 2, cb = t & 3;
#pragma unroll
    for (int u = 0; u < 4; u++) {
        int c = cb + u * 4;
        float4 v = *(const float4*)(g + r * 64 + c * 4);
        dst[c*4+0][r] = v.x * scale; dst[c*4+1][r] = v.y * scale;
        dst[c*4+2][r] = v.z * scale; dst[c*4+3][r] = v.w * scale;
    }
}

__device__ __forceinline__ void load_tile_N(float (*dst)[64], const float* __restrict__ g) {
    // global [row][64] -> smem [row][64]
    int t = threadIdx.x;
#pragma unroll
    for (int u = 0; u < 4; u++) {
        int idx = t + u * 256;
        int r = idx >> 4, c = idx & 15;
        *(float4*)&dst[r][c*4] = *(const float4*)(g + idx * 4);
    }
}

__global__ void attn_kernel() {
    __shared__ float QsT[64][64];   // [d][q], pre-scaled
    __shared__ float KVs[64][64];   // K phase: [d][kv] ; V phase: [kv][d]
    __shared__ float Ss[64][64];    // [q][kv] probabilities

    const int bh = blockIdx.y;
    const int q0 = blockIdx.x * 64;
    const int t  = threadIdx.x;
    const int tx = t & 15, ty = t >> 4;
    const int ty4 = ty * 4, tx4 = tx * 4;

    load_tile_T(QsT, g_Q + (bh * Ll + q0) * HD, SMSCALE);

    float m_i[4], l_i[4], O[4][4];
#pragma unroll
    for (int i = 0; i < 4; i++) {
        m_i[i] = -INFINITY; l_i[i] = 0.0f;
#pragma unroll
        for (int j = 0; j < 4; j++) O[i][j] = 0.0f;
    }

    for (int kt = 0; kt < LKV / 64; kt++) {
        __syncthreads();                                         // prev PV done
        load_tile_T(KVs, g_K + (bh * LKV + kt * 64) * HD, 1.0f); // K transposed
        __syncthreads();

        // S = Q K^T  (4x4 per thread; q rows = ty4+i, kv cols = tx4+j)
        float s[4][4] = {};
#pragma unroll 16
        for (int d = 0; d < 64; d++) {
            float4 a4 = *(const float4*)&QsT[d][ty4];
            float4 b4 = *(const float4*)&KVs[d][tx4];
            float av[4] = {a4.x, a4.y, a4.z, a4.w};
            float bv[4] = {b4.x, b4.y, b4.z, b4.w};
#pragma unroll
            for (int i = 0; i < 4; i++)
#pragma unroll
                for (int j = 0; j < 4; j++)
                    s[i][j] = fmaf(av[i], bv[j], s[i][j]);
        }

        // Online softmax per q-row; reductions across 16 tx lanes (half-warp)
#pragma unroll
        for (int i = 0; i < 4; i++) {
            float mx = fmaxf(fmaxf(s[i][0], s[i][1]), fmaxf(s[i][2], s[i][3]));
#pragma unroll
            for (int o = 1; o < 16; o <<= 1)
                mx = fmaxf(mx, __shfl_xor_sync(0xffffffffu, mx, o));
            float mnew = fmaxf(m_i[i], mx);
            float corr = __expf(m_i[i] - mnew);
            m_i[i] = mnew;
            float rs = 0.0f;
#pragma unroll
            for (int j = 0; j < 4; j++) {
                float p = __expf(s[i][j] - mnew);
                s[i][j] = p; rs += p;
            }
#pragma unroll
            for (int o = 1; o < 16; o <<= 1)
                rs += __shfl_xor_sync(0xffffffffu, rs, o);
            l_i[i] = l_i[i] * corr + rs;
#pragma unroll
            for (int j = 0; j < 4; j++) {
                O[i][j] *= corr;
                Ss[ty4 + i][tx4 + j] = s[i][j];
            }
        }
        __syncthreads();                                          // S visible, K consumed
        load_tile_N(KVs, g_V + (bh * LKV + kt * 64) * HD);        // V natural layout
        __syncthreads();

        // O += P V  (kv index rotated by ty*4 to avoid Ss bank conflicts)
#pragma unroll 8
        for (int kv0 = 0; kv0 < 64; kv0++) {
            int kvr = (kv0 + ty4) & 63;
            float4 v4 = *(const float4*)&KVs[kvr][tx4];
            float vv[4] = {v4.x, v4.y, v4.z, v4.w};
#pragma unroll
            for (int i = 0; i < 4; i++) {
                float p = Ss[ty4 + i][kvr];
#pragma unroll
                for (int j = 0; j < 4; j++)
                    O[i][j] = fmaf(p, vv[j], O[i][j]);
            }
        }
    }

    // Normalize and write to g_Ctx in [b*L + l][h*64 + d] layout
    const int h = bh % Hh, b = bh / Hh;
#pragma unroll
    for (int i = 0; i < 4; i++) {
        float inv = 1.0f / l_i[i];
        int q = q0 + ty4 + i;
        float4 o = make_float4(O[i][0]*inv, O[i][1]*inv, O[i][2]*inv, O[i][3]*inv);
        *(float4*)&g_Ctx[(b * Ll + q) * Dd + h * HD + tx4] = o;
    }
}

// ---------------------------------------------------------------------------
// 4) Output projection: out = Ctx @ Wo + bo
// ---------------------------------------------------------------------------
__global__ void oproj_kernel(const float* __restrict__ Wo,
                             const float* __restrict__ bo,
                             float* __restrict__ out) {
    __shared__ float As[16][68];
    __shared__ float Bs[16][64];

    const int m0 = blockIdx.y * 64;
    const int n0 = blockIdx.x * 64;
    const int t  = threadIdx.x;
    const int tx = t & 15, ty = t >> 4;
    const int ar = t >> 2, ac = t & 3;
    const int br = t >> 4, bc = t & 15;

    float acc[4][4] = {};
    const float* Ap = g_Ctx + (m0 + ar) * Dd + ac * 4;

    for (int k0 = 0; k0 < Dd; k0 += 16) {
        float4 xa = *(const float4*)(Ap + k0);
        float4 wb = *(const float4*)(Wo + (k0 + br) * Dd + n0 + bc * 4);
        __syncthreads();
        As[ac*4+0][ar] = xa.x; As[ac*4+1][ar] = xa.y;
        As[ac*4+2][ar] = xa.z; As[ac*4+3][ar] = xa.w;
        *(float4*)&Bs[br][bc*4] = wb;
        __syncthreads();
#pragma unroll
        for (int k = 0; k < 16; k++) {
            float4 a4 = *(const float4*)&As[k][ty*4];
            float4 b4 = *(const float4*)&Bs[k][tx*4];
            float av[4] = {a4.x, a4.y, a4.z, a4.w};
            float bv[4] = {b4.x, b4.y, b4.z, b4.w};
#pragma unroll
            for (int i = 0; i < 4; i++)
#pragma unroll
                for (int j = 0; j < 4; j++)
                    acc[i][j] = fmaf(av[i], bv[j], acc[i][j]);
        }
    }

    float4 bias = *(const float4*)(bo + n0 + tx * 4);
    float bv[4] = {bias.x, bias.y, bias.z, bias.w};
#pragma unroll
    for (int i = 0; i < 4; i++) {
        int m = m0 + ty * 4 + i;
        float4 v = make_float4(acc[i][0] + bv[0], acc[i][1] + bv[1],
                               acc[i][2] + bv[2], acc[i][3] + bv[3]);
        *(float4*)&out[m * Dd + n0 + tx * 4] = v;
    }
}

// ---------------------------------------------------------------------------
extern "C" void kernel_launch(void* const* d_in, const int* in_sizes, int n_in,
                              void* d_out, int out_size) {
    const float* X   = (const float*)d_in[0];
    const float* Kbg = (const float*)d_in[1];
    const float* Vbg = (const float*)d_in[2];
    const float* Wq  = (const float*)d_in[3];
    const float* Wk  = (const float*)d_in[4];
    const float* Wv  = (const float*)d_in[5];
    const float* Wo  = (const float*)d_in[6];
    const float* bo  = (const float*)d_in[7];
    float* out = (float*)d_out;

    bg_copy_kernel<<<5120, 256>>>((const float4*)Kbg, (const float4*)Vbg);
    proj_kernel<<<dim3(20, 64, 3), 256>>>(X, Wq, Wk, Wv);
    attn_kernel<<<dim3(16, 80), 256>>>();
    oproj_kernel<<<dim3(20, 64), 256>>>(Wo, bo, out);
}

// round 2
// speedup vs baseline: 1.3868x; 1.3868x over previous
#include <cuda_runtime.h>
#include <math.h>
#include <stdint.h>

// Problem constants
#define Bb   4
#define Ll   1024
#define Dd   1280
#define Hh   20
#define HD   64
#define BH   (Bb*Hh)        // 80
#define LKV  (2*Ll)         // 2048
#define Mm   (Bb*Ll)        // 4096
#define ALPHA 0.48f
#define SMSCALE 0.125f      // 1/sqrt(64)

// Persistent scratch (device globals; no allocation allowed)
__device__ float g_Q[BH * Ll * HD];          // [bh][q][d]
__device__ float g_K[BH * LKV * HD];         // [bh][kv][d]
__device__ float g_V[BH * LKV * HD];         // [bh][kv][d]
__device__ float g_Ctx[Mm * Dd];             // [b*L + l][h*64 + d]

// ---------------------------------------------------------------------------
// tf32 helpers
// ---------------------------------------------------------------------------
__device__ __forceinline__ uint32_t f2tf(float f) {
    uint32_t r;
    asm("cvt.rna.tf32.f32 %0, %1;" : "=r"(r) : "f"(f));
    return r;
}

__device__ __forceinline__ void mma_tf32(float* c, const uint32_t* a, const uint32_t* b) {
    asm volatile(
        "mma.sync.aligned.m16n8k8.row.col.f32.tf32.tf32.f32 "
        "{%0,%1,%2,%3}, {%4,%5,%6,%7}, {%8,%9}, {%0,%1,%2,%3};"
        : "+f"(c[0]), "+f"(c[1]), "+f"(c[2]), "+f"(c[3])
        : "r"(a[0]), "r"(a[1]), "r"(a[2]), "r"(a[3]), "r"(b[0]), "r"(b[1]));
}

// ---------------------------------------------------------------------------
// 1) Scale-copy the context-bank KV into the back half of g_K / g_V
// ---------------------------------------------------------------------------
__global__ void bg_copy_kernel(const float4* __restrict__ Kbg,
                               const float4* __restrict__ Vbg) {
    int i = blockIdx.x * blockDim.x + threadIdx.x;
    const int NBG4 = BH * Ll * (HD / 4);
    if (i >= NBG4) return;
    int bh  = i >> 14;
    int rem = i & 16383;
    int dst = bh * (LKV * HD / 4) + (Ll * HD / 4) + rem;
    float4 k = Kbg[i];
    float4 v = Vbg[i];
    k.x *= ALPHA; k.y *= ALPHA; k.z *= ALPHA; k.w *= ALPHA;
    v.x *= ALPHA; v.y *= ALPHA; v.z *= ALPHA; v.w *= ALPHA;
    ((float4*)g_K)[dst] = k;
    ((float4*)g_V)[dst] = v;
}

// ---------------------------------------------------------------------------
// tf32 GEMM tiles: BM=128, BN=64, BK=16; 256 threads = 8 warps (4m x 2n),
// each warp computes 32x32 via m16n8k8 (2 m-tiles x 4 n-tiles).
// ---------------------------------------------------------------------------
#define PA 20   // As row stride (uint32)
#define PB 72   // Bs row stride (uint32)

struct Frag {
    float acc[2][4][4];
};

// global->reg loaders (fp32)
__device__ __forceinline__ void g_load_A(float4* ra, const float* __restrict__ A,
                                         int m0, int k0, int t) {
    int row = t >> 1, cg = (t & 1) * 8;
    const float* p = A + (m0 + row) * Dd + k0 + cg;
    ra[0] = *(const float4*)p;
    ra[1] = *(const float4*)(p + 4);
}
__device__ __forceinline__ void g_load_B(float4* rb, const float* __restrict__ W,
                                         int n0, int k0, int t) {
    int row = t >> 4, c4 = (t & 15) * 4;
    rb[0] = *(const float4*)(W + (k0 + row) * Dd + n0 + c4);
}
// reg->smem (cvt to tf32)
__device__ __forceinline__ void s_store_A(uint32_t* As, const float4* ra, int t) {
    int row = t >> 1, cg = (t & 1) * 8;
    uint32_t* p = As + row * PA + cg;
    p[0] = f2tf(ra[0].x); p[1] = f2tf(ra[0].y); p[2] = f2tf(ra[0].z); p[3] = f2tf(ra[0].w);
    p[4] = f2tf(ra[1].x); p[5] = f2tf(ra[1].y); p[6] = f2tf(ra[1].z); p[7] = f2tf(ra[1].w);
}
__device__ __forceinline__ void s_store_B(uint32_t* Bs, const float4* rb, int t) {
    int row = t >> 4, c4 = (t & 15) * 4;
    uint32_t* p = Bs + row * PB + c4;
    p[0] = f2tf(rb[0].x); p[1] = f2tf(rb[0].y); p[2] = f2tf(rb[0].z); p[3] = f2tf(rb[0].w);
}

__device__ __forceinline__ void compute_tile(Frag& F, const uint32_t* __restrict__ As,
                                             const uint32_t* __restrict__ Bs, int t) {
    const int lane = t & 31, w = t >> 5;
    const int g = lane >> 2, tig = lane & 3;
    const int wm = (w >> 1) * 32, wn = (w & 1) * 32;
    uint32_t a[2][4], b[4][2];
#pragma unroll
    for (int kk = 0; kk < 16; kk += 8) {
#pragma unroll
        for (int mt = 0; mt < 2; mt++) {
            int r = wm + mt * 16 + g;
            a[mt][0] = As[r * PA + kk + tig];
            a[mt][1] = As[(r + 8) * PA + kk + tig];
            a[mt][2] = As[r * PA + kk + tig + 4];
            a[mt][3] = As[(r + 8) * PA + kk + tig + 4];
        }
#pragma unroll
        for (int nt = 0; nt < 4; nt++) {
            int c = wn + nt * 8 + g;
            b[nt][0] = Bs[(kk + tig) * PB + c];
            b[nt][1] = Bs[(kk + tig + 4) * PB + c];
        }
#pragma unroll
        for (int mt = 0; mt < 2; mt++)
#pragma unroll
            for (int nt = 0; nt < 4; nt++)
                mma_tf32(F.acc[mt][nt], a[mt], b[nt]);
    }
}

// ---------------------------------------------------------------------------
// 2) QKV projection GEMM (tensor cores), scatter to head layout
// ---------------------------------------------------------------------------
__global__ void proj_kernel(const float* __restrict__ X,
                            const float* __restrict__ Wq,
                            const float* __restrict__ Wk,
                            const float* __restrict__ Wv) {
    __shared__ uint32_t As[2][128 * PA];
    __shared__ uint32_t Bs[2][16 * PB];

    const int m0 = blockIdx.y * 128;
    const int n0 = blockIdx.x * 64;
    const int z  = blockIdx.z;
    const float* __restrict__ W = (z == 0) ? Wq : ((z == 1) ? Wk : Wv);
    const int t = threadIdx.x;

    Frag F;
#pragma unroll
    for (int mt = 0; mt < 2; mt++)
#pragma unroll
        for (int nt = 0; nt < 4; nt++)
#pragma unroll
            for (int i = 0; i < 4; i++) F.acc[mt][nt][i] = 0.0f;

    float4 ra[2], rb[1];
    g_load_A(ra, X, m0, 0, t);
    g_load_B(rb, W, n0, 0, t);
    s_store_A(As[0], ra, t);
    s_store_B(Bs[0], rb, t);
    __syncthreads();

    int cur = 0;
    for (int k0 = 16; k0 < Dd; k0 += 16) {
        g_load_A(ra, X, m0, k0, t);
        g_load_B(rb, W, n0, k0, t);
        compute_tile(F, As[cur], Bs[cur], t);
        s_store_A(As[cur ^ 1], ra, t);
        s_store_B(Bs[cur ^ 1], rb, t);
        __syncthreads();
        cur ^= 1;
    }
    compute_tile(F, As[cur], Bs[cur], t);

    // Epilogue: scatter to head-batched layout (block covers one 64-wide head)
    const int lane = t & 31, w = t >> 5;
    const int g = lane >> 2, tig = lane & 3;
    const int wm = (w >> 1) * 32, wn = (w & 1) * 32;
    const int h = blockIdx.x;   // n0/64
#pragma unroll
    for (int mt = 0; mt < 2; mt++) {
#pragma unroll
        for (int half = 0; half < 2; half++) {
            int m = m0 + wm + mt * 16 + g + half * 8;
            int b = m >> 10, l = m & 1023;
#pragma unroll
            for (int nt = 0; nt < 4; nt++) {
                int col = wn + nt * 8 + 2 * tig;
                float2 v = make_float2(F.acc[mt][nt][half * 2 + 0],
                                       F.acc[mt][nt][half * 2 + 1]);
                if (z == 0)
                    *(float2*)&g_Q[((b * Hh + h) * Ll + l) * HD + col] = v;
                else if (z == 1)
                    *(float2*)&g_K[((b * Hh + h) * LKV + l) * HD + col] = v;
                else
                    *(float2*)&g_V[((b * Hh + h) * LKV + l) * HD + col] = v;
            }
        }
    }
}

// ---------------------------------------------------------------------------
// 3) Flash attention (SIMT fp32, unchanged from R1)
// ---------------------------------------------------------------------------
__device__ __forceinline__ void load_tile_T(float (*dst)[64], const float* __restrict__ g,
                                            float scale) {
    int t = threadIdx.x;
    int r = t >> 2, cb = t & 3;
#pragma unroll
    for (int u = 0; u < 4; u++) {
        int c = cb + u * 4;
        float4 v = *(const float4*)(g + r * 64 + c * 4);
        dst[c*4+0][r] = v.x * scale; dst[c*4+1][r] = v.y * scale;
        dst[c*4+2][r] = v.z * scale; dst[c*4+3][r] = v.w * scale;
    }
}

__device__ __forceinline__ void load_tile_N(float (*dst)[64], const float* __restrict__ g) {
    int t = threadIdx.x;
#pragma unroll
    for (int u = 0; u < 4; u++) {
        int idx = t + u * 256;
        int r = idx >> 4, c = idx & 15;
        *(float4*)&dst[r][c*4] = *(const float4*)(g + idx * 4);
    }
}

__global__ void attn_kernel() {
    __shared__ float QsT[64][64];
    __shared__ float KVs[64][64];
    __shared__ float Ss[64][64];

    const int bh = blockIdx.y;
    const int q0 = blockIdx.x * 64;
    const int t  = threadIdx.x;
    const int tx = t & 15, ty = t >> 4;
    const int ty4 = ty * 4, tx4 = tx * 4;

    load_tile_T(QsT, g_Q + (bh * Ll + q0) * HD, SMSCALE);

    float m_i[4], l_i[4], O[4][4];
#pragma unroll
    for (int i = 0; i < 4; i++) {
        m_i[i] = -INFINITY; l_i[i] = 0.0f;
#pragma unroll
        for (int j = 0; j < 4; j++) O[i][j] = 0.0f;
    }

    for (int kt = 0; kt < LKV / 64; kt++) {
        __syncthreads();
        load_tile_T(KVs, g_K + (bh * LKV + kt * 64) * HD, 1.0f);
        __syncthreads();

        float s[4][4] = {};
#pragma unroll 16
        for (int d = 0; d < 64; d++) {
            float4 a4 = *(const float4*)&QsT[d][ty4];
            float4 b4 = *(const float4*)&KVs[d][tx4];
            float av[4] = {a4.x, a4.y, a4.z, a4.w};
            float bv[4] = {b4.x, b4.y, b4.z, b4.w};
#pragma unroll
            for (int i = 0; i < 4; i++)
#pragma unroll
                for (int j = 0; j < 4; j++)
                    s[i][j] = fmaf(av[i], bv[j], s[i][j]);
        }

#pragma unroll
        for (int i = 0; i < 4; i++) {
            float mx = fmaxf(fmaxf(s[i][0], s[i][1]), fmaxf(s[i][2], s[i][3]));
#pragma unroll
            for (int o = 1; o < 16; o <<= 1)
                mx = fmaxf(mx, __shfl_xor_sync(0xffffffffu, mx, o));
            float mnew = fmaxf(m_i[i], mx);
            float corr = __expf(m_i[i] - mnew);
            m_i[i] = mnew;
            float rs = 0.0f;
#pragma unroll
            for (int j = 0; j < 4; j++) {
                float p = __expf(s[i][j] - mnew);
                s[i][j] = p; rs += p;
            }
#pragma unroll
            for (int o = 1; o < 16; o <<= 1)
                rs += __shfl_xor_sync(0xffffffffu, rs, o);
            l_i[i] = l_i[i] * corr + rs;
#pragma unroll
            for (int j = 0; j < 4; j++) {
                O[i][j] *= corr;
                Ss[ty4 + i][tx4 + j] = s[i][j];
            }
        }
        __syncthreads();
        load_tile_N(KVs, g_V + (bh * LKV + kt * 64) * HD);
        __syncthreads();

#pragma unroll 8
        for (int kv0 = 0; kv0 < 64; kv0++) {
            int kvr = (kv0 + ty4) & 63;
            float4 v4 = *(const float4*)&KVs[kvr][tx4];
            float vv[4] = {v4.x, v4.y, v4.z, v4.w};
#pragma unroll
            for (int i = 0; i < 4; i++) {
                float p = Ss[ty4 + i][kvr];
#pragma unroll
                for (int j = 0; j < 4; j++)
                    O[i][j] = fmaf(p, vv[j], O[i][j]);
            }
        }
    }

    const int h = bh % Hh, b = bh / Hh;
#pragma unroll
    for (int i = 0; i < 4; i++) {
        float inv = 1.0f / l_i[i];
        int q = q0 + ty4 + i;
        float4 o = make_float4(O[i][0]*inv, O[i][1]*inv, O[i][2]*inv, O[i][3]*inv);
        *(float4*)&g_Ctx[(b * Ll + q) * Dd + h * HD + tx4] = o;
    }
}

// ---------------------------------------------------------------------------
// 4) Output projection: out = Ctx @ Wo + bo  (tensor cores)
// ---------------------------------------------------------------------------
__global__ void oproj_kernel(const float* __restrict__ Wo,
                             const float* __restrict__ bo,
                             float* __restrict__ out) {
    __shared__ uint32_t As[2][128 * PA];
    __shared__ uint32_t Bs[2][16 * PB];

    const int m0 = blockIdx.y * 128;
    const int n0 = blockIdx.x * 64;
    const int t = threadIdx.x;

    Frag F;
#pragma unroll
    for (int mt = 0; mt < 2; mt++)
#pragma unroll
        for (int nt = 0; nt < 4; nt++)
#pragma unroll
            for (int i = 0; i < 4; i++) F.acc[mt][nt][i] = 0.0f;

    float4 ra[2], rb[1];
    g_load_A(ra, g_Ctx, m0, 0, t);
    g_load_B(rb, Wo, n0, 0, t);
    s_store_A(As[0], ra, t);
    s_store_B(Bs[0], rb, t);
    __syncthreads();

    int cur = 0;
    for (int k0 = 16; k0 < Dd; k0 += 16) {
        g_load_A(ra, g_Ctx, m0, k0, t);
        g_load_B(rb, Wo, n0, k0, t);
        compute_tile(F, As[cur], Bs[cur], t);
        s_store_A(As[cur ^ 1], ra, t);
        s_store_B(Bs[cur ^ 1], rb, t);
        __syncthreads();
        cur ^= 1;
    }
    compute_tile(F, As[cur], Bs[cur], t);

    const int lane = t & 31, w = t >> 5;
    const int g = lane >> 2, tig = lane & 3;
    const int wm = (w >> 1) * 32, wn = (w & 1) * 32;
#pragma unroll
    for (int mt = 0; mt < 2; mt++) {
#pragma unroll
        for (int half = 0; half < 2; half++) {
            int m = m0 + wm + mt * 16 + g + half * 8;
#pragma unroll
            for (int nt = 0; nt < 4; nt++) {
                int col = wn + nt * 8 + 2 * tig;
                float2 bias = *(const float2*)(bo + n0 + col);
                float2 v = make_float2(F.acc[mt][nt][half * 2 + 0] + bias.x,
                                       F.acc[mt][nt][half * 2 + 1] + bias.y);
                *(float2*)&out[m * Dd + n0 + col] = v;
            }
        }
    }
}

// ---------------------------------------------------------------------------
extern "C" void kernel_launch(void* const* d_in, const int* in_sizes, int n_in,
                              void* d_out, int out_size) {
    const float* X   = (const float*)d_in[0];
    const float* Kbg = (const float*)d_in[1];
    const float* Vbg = (const float*)d_in[2];
    const float* Wq  = (const float*)d_in[3];
    const float* Wk  = (const float*)d_in[4];
    const float* Wv  = (const float*)d_in[5];
    const float* Wo  = (const float*)d_in[6];
    const float* bo  = (const float*)d_in[7];
    float* out = (float*)d_out;

    bg_copy_kernel<<<5120, 256>>>((const float4*)Kbg, (const float4*)Vbg);
    proj_kernel<<<dim3(20, 32, 3), 256>>>(X, Wq, Wk, Wv);
    attn_kernel<<<dim3(16, 80), 256>>>();
    oproj_kernel<<<dim3(20, 32), 256>>>(Wo, bo, out);
}

// round 3
// speedup vs baseline: 1.9282x; 1.3904x over previous
#include <cuda_runtime.h>
#include <math.h>
#include <stdint.h>

// Problem constants
#define Bb   4
#define Ll   1024
#define Dd   1280
#define Hh   20
#define HD   64
#define BH   (Bb*Hh)        // 80
#define LKV  (2*Ll)         // 2048
#define Mm   (Bb*Ll)        // 4096
#define ALPHA 0.48f
#define SMSCALE 0.125f      // 1/sqrt(64)

// Persistent scratch (device globals; no allocation allowed)
__device__ float g_Q[BH * Ll * HD];          // [bh][q][d]
__device__ float g_K[BH * LKV * HD];         // [bh][kv][d]
__device__ float g_V[BH * LKV * HD];         // [bh][kv][d]
__device__ float g_Ctx[Mm * Dd];             // [b*L + l][h*64 + d]

// ---------------------------------------------------------------------------
// tf32 helpers
// ---------------------------------------------------------------------------
__device__ __forceinline__ uint32_t f2tf(float f) {
    uint32_t r;
    asm("cvt.rna.tf32.f32 %0, %1;" : "=r"(r) : "f"(f));
    return r;
}

__device__ __forceinline__ void mma_tf32(float* c, const uint32_t* a, const uint32_t* b) {
    asm volatile(
        "mma.sync.aligned.m16n8k8.row.col.f32.tf32.tf32.f32 "
        "{%0,%1,%2,%3}, {%4,%5,%6,%7}, {%8,%9}, {%0,%1,%2,%3};"
        : "+f"(c[0]), "+f"(c[1]), "+f"(c[2]), "+f"(c[3])
        : "r"(a[0]), "r"(a[1]), "r"(a[2]), "r"(a[3]), "r"(b[0]), "r"(b[1]));
}

// ---------------------------------------------------------------------------
// 1) Scale-copy the context-bank KV into the back half of g_K / g_V
// ---------------------------------------------------------------------------
__global__ void bg_copy_kernel(const float4* __restrict__ Kbg,
                               const float4* __restrict__ Vbg) {
    int i = blockIdx.x * blockDim.x + threadIdx.x;
    const int NBG4 = BH * Ll * (HD / 4);
    if (i >= NBG4) return;
    int bh  = i >> 14;
    int rem = i & 16383;
    int dst = bh * (LKV * HD / 4) + (Ll * HD / 4) + rem;
    float4 k = Kbg[i];
    float4 v = Vbg[i];
    k.x *= ALPHA; k.y *= ALPHA; k.z *= ALPHA; k.w *= ALPHA;
    v.x *= ALPHA; v.y *= ALPHA; v.z *= ALPHA; v.w *= ALPHA;
    ((float4*)g_K)[dst] = k;
    ((float4*)g_V)[dst] = v;
}

// ---------------------------------------------------------------------------
// tf32 GEMM tiles: BM=128, BN=64, BK=16; 256 threads = 8 warps (4m x 2n)
// ---------------------------------------------------------------------------
#define PA 20   // As row stride (uint32)
#define PB 72   // Bs row stride (uint32)

struct Frag {
    float acc[2][4][4];
};

__device__ __forceinline__ void g_load_A(float4* ra, const float* __restrict__ A,
                                         int m0, int k0, int t) {
    int row = t >> 1, cg = (t & 1) * 8;
    const float* p = A + (m0 + row) * Dd + k0 + cg;
    ra[0] = *(const float4*)p;
    ra[1] = *(const float4*)(p + 4);
}
__device__ __forceinline__ void g_load_B(float4* rb, const float* __restrict__ W,
                                         int n0, int k0, int t) {
    int row = t >> 4, c4 = (t & 15) * 4;
    rb[0] = *(const float4*)(W + (k0 + row) * Dd + n0 + c4);
}
__device__ __forceinline__ void s_store_A(uint32_t* As, const float4* ra, int t) {
    int row = t >> 1, cg = (t & 1) * 8;
    uint32_t* p = As + row * PA + cg;
    p[0] = f2tf(ra[0].x); p[1] = f2tf(ra[0].y); p[2] = f2tf(ra[0].z); p[3] = f2tf(ra[0].w);
    p[4] = f2tf(ra[1].x); p[5] = f2tf(ra[1].y); p[6] = f2tf(ra[1].z); p[7] = f2tf(ra[1].w);
}
__device__ __forceinline__ void s_store_B(uint32_t* Bs, const float4* rb, int t) {
    int row = t >> 4, c4 = (t & 15) * 4;
    uint32_t* p = Bs + row * PB + c4;
    p[0] = f2tf(rb[0].x); p[1] = f2tf(rb[0].y); p[2] = f2tf(rb[0].z); p[3] = f2tf(rb[0].w);
}

__device__ __forceinline__ void compute_tile(Frag& F, const uint32_t* __restrict__ As,
                                             const uint32_t* __restrict__ Bs, int t) {
    const int lane = t & 31, w = t >> 5;
    const int g = lane >> 2, tig = lane & 3;
    const int wm = (w >> 1) * 32, wn = (w & 1) * 32;
    uint32_t a[2][4], b[4][2];
#pragma unroll
    for (int kk = 0; kk < 16; kk += 8) {
#pragma unroll
        for (int mt = 0; mt < 2; mt++) {
            int r = wm + mt * 16 + g;
            a[mt][0] = As[r * PA + kk + tig];
            a[mt][1] = As[(r + 8) * PA + kk + tig];
            a[mt][2] = As[r * PA + kk + tig + 4];
            a[mt][3] = As[(r + 8) * PA + kk + tig + 4];
        }
#pragma unroll
        for (int nt = 0; nt < 4; nt++) {
            int c = wn + nt * 8 + g;
            b[nt][0] = Bs[(kk + tig) * PB + c];
            b[nt][1] = Bs[(kk + tig + 4) * PB + c];
        }
#pragma unroll
        for (int mt = 0; mt < 2; mt++)
#pragma unroll
            for (int nt = 0; nt < 4; nt++)
                mma_tf32(F.acc[mt][nt], a[mt], b[nt]);
    }
}

// ---------------------------------------------------------------------------
// 2) QKV projection GEMM (tensor cores), scatter to head layout
// ---------------------------------------------------------------------------
__global__ void proj_kernel(const float* __restrict__ X,
                            const float* __restrict__ Wq,
                            const float* __restrict__ Wk,
                            const float* __restrict__ Wv) {
    __shared__ uint32_t As[2][128 * PA];
    __shared__ uint32_t Bs[2][16 * PB];

    const int m0 = blockIdx.y * 128;
    const int n0 = blockIdx.x * 64;
    const int z  = blockIdx.z;
    const float* __restrict__ W = (z == 0) ? Wq : ((z == 1) ? Wk : Wv);
    const int t = threadIdx.x;

    Frag F;
#pragma unroll
    for (int mt = 0; mt < 2; mt++)
#pragma unroll
        for (int nt = 0; nt < 4; nt++)
#pragma unroll
            for (int i = 0; i < 4; i++) F.acc[mt][nt][i] = 0.0f;

    float4 ra[2], rb[1];
    g_load_A(ra, X, m0, 0, t);
    g_load_B(rb, W, n0, 0, t);
    s_store_A(As[0], ra, t);
    s_store_B(Bs[0], rb, t);
    __syncthreads();

    int cur = 0;
    for (int k0 = 16; k0 < Dd; k0 += 16) {
        g_load_A(ra, X, m0, k0, t);
        g_load_B(rb, W, n0, k0, t);
        compute_tile(F, As[cur], Bs[cur], t);
        s_store_A(As[cur ^ 1], ra, t);
        s_store_B(Bs[cur ^ 1], rb, t);
        __syncthreads();
        cur ^= 1;
    }
    compute_tile(F, As[cur], Bs[cur], t);

    const int lane = t & 31, w = t >> 5;
    const int g = lane >> 2, tig = lane & 3;
    const int wm = (w >> 1) * 32, wn = (w & 1) * 32;
    const int h = blockIdx.x;
#pragma unroll
    for (int mt = 0; mt < 2; mt++) {
#pragma unroll
        for (int half = 0; half < 2; half++) {
            int m = m0 + wm + mt * 16 + g + half * 8;
            int b = m >> 10, l = m & 1023;
#pragma unroll
            for (int nt = 0; nt < 4; nt++) {
                int col = wn + nt * 8 + 2 * tig;
                float2 v = make_float2(F.acc[mt][nt][half * 2 + 0],
                                       F.acc[mt][nt][half * 2 + 1]);
                if (z == 0)
                    *(float2*)&g_Q[((b * Hh + h) * Ll + l) * HD + col] = v;
                else if (z == 1)
                    *(float2*)&g_K[((b * Hh + h) * LKV + l) * HD + col] = v;
                else
                    *(float2*)&g_V[((b * Hh + h) * LKV + l) * HD + col] = v;
            }
        }
    }
}

// ---------------------------------------------------------------------------
// 3) Flash attention on tensor cores (tf32; split-tf32 for QK^T)
//    Block: 128 threads = 4 warps; warp w owns q rows [w*16, w*16+16).
//    KV tile = 32. Q frags persistent in registers (hi/lo).
// ---------------------------------------------------------------------------
__global__ void __launch_bounds__(128) attn_kernel() {
    __shared__ uint32_t Khi[32][68];   // K tile [kv][d] tf32-hi
    __shared__ uint32_t Klo[32][68];   // K tile residual
    __shared__ uint32_t VTs[64][36];   // V tile transposed [d][kv]
    __shared__ uint32_t Ps [64][36];   // P tile [q][kv] tf32

    const int bh = blockIdx.y;
    const int q0 = blockIdx.x * 64;
    const int t = threadIdx.x;
    const int w = t >> 5, lane = t & 31;
    const int g = lane >> 2, tig = lane & 3;
    const int qw = w * 16;

    // Q fragments: split hi/lo, pre-scaled (scale is exact power of 2)
    uint32_t qhi[8][4], qlo[8][4];
    {
        const float* Qp = g_Q + (bh * Ll + q0 + qw) * HD;
#pragma unroll
        for (int kk = 0; kk < 8; kk++) {
            int c0 = kk * 8 + tig;
            float x[4];
            x[0] = Qp[g * HD + c0] * SMSCALE;
            x[1] = Qp[(g + 8) * HD + c0] * SMSCALE;
            x[2] = Qp[g * HD + c0 + 4] * SMSCALE;
            x[3] = Qp[(g + 8) * HD + c0 + 4] * SMSCALE;
#pragma unroll
            for (int i = 0; i < 4; i++) {
                uint32_t hi = f2tf(x[i]);
                qhi[kk][i] = hi;
                qlo[kk][i] = f2tf(x[i] - __uint_as_float(hi));
            }
        }
    }

    float o[8][4];
#pragma unroll
    for (int nt = 0; nt < 8; nt++)
#pragma unroll
        for (int i = 0; i < 4; i++) o[nt][i] = 0.0f;
    float m0 = -INFINITY, m1 = -INFINITY, l0 = 0.0f, l1 = 0.0f;

    const float4* Kg = (const float4*)(g_K + (size_t)bh * LKV * HD);
    const float4* Vg = (const float4*)(g_V + (size_t)bh * LKV * HD);

    for (int kt = 0; kt < LKV / 32; kt++) {
        __syncthreads();   // previous iteration's smem reads complete
        int base4 = kt * 32 * 16;     // 32 rows x 16 float4
#pragma unroll
        for (int u = 0; u < 4; u++) {
            int idx4 = u * 128 + t;
            int row = idx4 >> 4, c4 = idx4 & 15;
            float4 kx = Kg[base4 + idx4];
            float4 vx = Vg[base4 + idx4];
            float kv[4] = {kx.x, kx.y, kx.z, kx.w};
            float vv[4] = {vx.x, vx.y, vx.z, vx.w};
#pragma unroll
            for (int j = 0; j < 4; j++) {
                uint32_t hi = f2tf(kv[j]);
                Khi[row][c4 * 4 + j] = hi;
                Klo[row][c4 * 4 + j] = f2tf(kv[j] - __uint_as_float(hi));
                VTs[c4 * 4 + j][row] = f2tf(vv[j]);
            }
        }
        __syncthreads();

        // S = Q K^T  (3-MMA split for near-fp32 scores)
        float s[4][4];
#pragma unroll
        for (int nt = 0; nt < 4; nt++)
#pragma unroll
            for (int i = 0; i < 4; i++) s[nt][i] = 0.0f;
#pragma unroll
        for (int kk = 0; kk < 8; kk++) {
#pragma unroll
            for (int nt = 0; nt < 4; nt++) {
                int c = nt * 8 + g;
                uint32_t bhi[2] = {Khi[c][kk * 8 + tig], Khi[c][kk * 8 + tig + 4]};
                uint32_t blo[2] = {Klo[c][kk * 8 + tig], Klo[c][kk * 8 + tig + 4]};
                mma_tf32(s[nt], qlo[kk], bhi);
                mma_tf32(s[nt], qhi[kk], blo);
                mma_tf32(s[nt], qhi[kk], bhi);
            }
        }

        // Online softmax: rows g (vals 0,1) and g+8 (vals 2,3)
        float mx0 = fmaxf(fmaxf(s[0][0], s[0][1]), fmaxf(s[1][0], s[1][1]));
        mx0 = fmaxf(mx0, fmaxf(fmaxf(s[2][0], s[2][1]), fmaxf(s[3][0], s[3][1])));
        float mx1 = fmaxf(fmaxf(s[0][2], s[0][3]), fmaxf(s[1][2], s[1][3]));
        mx1 = fmaxf(mx1, fmaxf(fmaxf(s[2][2], s[2][3]), fmaxf(s[3][2], s[3][3])));
#pragma unroll
        for (int off = 1; off < 4; off <<= 1) {
            mx0 = fmaxf(mx0, __shfl_xor_sync(0xffffffffu, mx0, off));
            mx1 = fmaxf(mx1, __shfl_xor_sync(0xffffffffu, mx1, off));
        }
        float mn0 = fmaxf(m0, mx0), mn1 = fmaxf(m1, mx1);
        float corr0 = __expf(m0 - mn0), corr1 = __expf(m1 - mn1);
        m0 = mn0; m1 = mn1;
        float rs0 = 0.0f, rs1 = 0.0f;
#pragma unroll
        for (int nt = 0; nt < 4; nt++) {
            float p00 = __expf(s[nt][0] - mn0);
            float p01 = __expf(s[nt][1] - mn0);
            float p10 = __expf(s[nt][2] - mn1);
            float p11 = __expf(s[nt][3] - mn1);
            rs0 += p00 + p01;
            rs1 += p10 + p11;
            int col = nt * 8 + 2 * tig;
            *(uint2*)&Ps[qw + g][col]     = make_uint2(f2tf(p00), f2tf(p01));
            *(uint2*)&Ps[qw + g + 8][col] = make_uint2(f2tf(p10), f2tf(p11));
        }
#pragma unroll
        for (int off = 1; off < 4; off <<= 1) {
            rs0 += __shfl_xor_sync(0xffffffffu, rs0, off);
            rs1 += __shfl_xor_sync(0xffffffffu, rs1, off);
        }
        l0 = l0 * corr0 + rs0;
        l1 = l1 * corr1 + rs1;
#pragma unroll
        for (int nt = 0; nt < 8; nt++) {
            o[nt][0] *= corr0; o[nt][1] *= corr0;
            o[nt][2] *= corr1; o[nt][3] *= corr1;
        }
        __syncwarp();

        // O += P V
#pragma unroll
        for (int kk = 0; kk < 4; kk++) {
            uint32_t a[4] = {Ps[qw + g][kk * 8 + tig],
                             Ps[qw + g + 8][kk * 8 + tig],
                             Ps[qw + g][kk * 8 + tig + 4],
                             Ps[qw + g + 8][kk * 8 + tig + 4]};
#pragma unroll
            for (int nt = 0; nt < 8; nt++) {
                int c = nt * 8 + g;
                uint32_t b[2] = {VTs[c][kk * 8 + tig], VTs[c][kk * 8 + tig + 4]};
                mma_tf32(o[nt], a, b);
            }
        }
    }

    // Normalize and write
    float inv0 = 1.0f / l0, inv1 = 1.0f / l1;
    const int h = bh % Hh, b = bh / Hh;
    int r0 = q0 + qw + g, r1 = r0 + 8;
#pragma unroll
    for (int nt = 0; nt < 8; nt++) {
        int col = h * HD + nt * 8 + 2 * tig;
        *(float2*)&g_Ctx[(b * Ll + r0) * Dd + col] =
            make_float2(o[nt][0] * inv0, o[nt][1] * inv0);
        *(float2*)&g_Ctx[(b * Ll + r1) * Dd + col] =
            make_float2(o[nt][2] * inv1, o[nt][3] * inv1);
    }
}

// ---------------------------------------------------------------------------
// 4) Output projection: out = Ctx @ Wo + bo  (tensor cores)
// ---------------------------------------------------------------------------
__global__ void oproj_kernel(const float* __restrict__ Wo,
                             const float* __restrict__ bo,
                             float* __restrict__ out) {
    __shared__ uint32_t As[2][128 * PA];
    __shared__ uint32_t Bs[2][16 * PB];

    const int m0 = blockIdx.y * 128;
    const int n0 = blockIdx.x * 64;
    const int t = threadIdx.x;

    Frag F;
#pragma unroll
    for (int mt = 0; mt < 2; mt++)
#pragma unroll
        for (int nt = 0; nt < 4; nt++)
#pragma unroll
            for (int i = 0; i < 4; i++) F.acc[mt][nt][i] = 0.0f;

    float4 ra[2], rb[1];
    g_load_A(ra, g_Ctx, m0, 0, t);
    g_load_B(rb, Wo, n0, 0, t);
    s_store_A(As[0], ra, t);
    s_store_B(Bs[0], rb, t);
    __syncthreads();

    int cur = 0;
    for (int k0 = 16; k0 < Dd; k0 += 16) {
        g_load_A(ra, g_Ctx, m0, k0, t);
        g_load_B(rb, Wo, n0, k0, t);
        compute_tile(F, As[cur], Bs[cur], t);
        s_store_A(As[cur ^ 1], ra, t);
        s_store_B(Bs[cur ^ 1], rb, t);
        __syncthreads();
        cur ^= 1;
    }
    compute_tile(F, As[cur], Bs[cur], t);

    const int lane = t & 31, w = t >> 5;
    const int g = lane >> 2, tig = lane & 3;
    const int wm = (w >> 1) * 32, wn = (w & 1) * 32;
#pragma unroll
    for (int mt = 0; mt < 2; mt++) {
#pragma unroll
        for (int half = 0; half < 2; half++) {
            int m = m0 + wm + mt * 16 + g + half * 8;
#pragma unroll
            for (int nt = 0; nt < 4; nt++) {
                int col = wn + nt * 8 + 2 * tig;
                float2 bias = *(const float2*)(bo + n0 + col);
                float2 v = make_float2(F.acc[mt][nt][half * 2 + 0] + bias.x,
                                       F.acc[mt][nt][half * 2 + 1] + bias.y);
                *(float2*)&out[m * Dd + n0 + col] = v;
            }
        }
    }
}

// ---------------------------------------------------------------------------
extern "C" void kernel_launch(void* const* d_in, const int* in_sizes, int n_in,
                              void* d_out, int out_size) {
    const float* X   = (const float*)d_in[0];
    const float* Kbg = (const float*)d_in[1];
    const float* Vbg = (const float*)d_in[2];
    const float* Wq  = (const float*)d_in[3];
    const float* Wk  = (const float*)d_in[4];
    const float* Wv  = (const float*)d_in[5];
    const float* Wo  = (const float*)d_in[6];
    const float* bo  = (const float*)d_in[7];
    float* out = (float*)d_out;

    bg_copy_kernel<<<5120, 256>>>((const float4*)Kbg, (const float4*)Vbg);
    proj_kernel<<<dim3(20, 32, 3), 256>>>(X, Wq, Wk, Wv);
    attn_kernel<<<dim3(16, 80), 128>>>();
    oproj_kernel<<<dim3(20, 32), 256>>>(Wo, bo, out);
}

// round 5
// speedup vs baseline: 2.1788x; 1.1299x over previous
#include <cuda_runtime.h>
#include <math.h>
#include <stdint.h>

// Problem constants
#define Bb   4
#define Ll   1024
#define Dd   1280
#define Hh   20
#define HD   64
#define BH   (Bb*Hh)        // 80
#define LKV  (2*Ll)         // 2048
#define Mm   (Bb*Ll)        // 4096
#define ALPHA 0.48f
#define SMSCALE 0.125f      // 1/sqrt(64)

// Persistent scratch (device globals; no allocation allowed)
__device__ float g_Q[BH * Ll * HD];          // [bh][q][d]
__device__ float g_K[BH * LKV * HD];         // [bh][kv][d]
__device__ float g_V[BH * LKV * HD];         // [bh][kv][d]
__device__ float g_Ctx[Mm * Dd];             // [b*L + l][h*64 + d]

// ---------------------------------------------------------------------------
// tf32 helpers
// ---------------------------------------------------------------------------
__device__ __forceinline__ uint32_t f2tf(float f) {
    uint32_t r;
    asm("cvt.rna.tf32.f32 %0, %1;" : "=r"(r) : "f"(f));
    return r;
}

__device__ __forceinline__ void mma_tf32(float* c, const uint32_t* a, const uint32_t* b) {
    asm volatile(
        "mma.sync.aligned.m16n8k8.row.col.f32.tf32.tf32.f32 "
        "{%0,%1,%2,%3}, {%4,%5,%6,%7}, {%8,%9}, {%0,%1,%2,%3};"
        : "+f"(c[0]), "+f"(c[1]), "+f"(c[2]), "+f"(c[3])
        : "r"(a[0]), "r"(a[1]), "r"(a[2]), "r"(a[3]), "r"(b[0]), "r"(b[1]));
}

// ---------------------------------------------------------------------------
// 1) Scale-copy the context-bank KV into the back half of g_K / g_V
// ---------------------------------------------------------------------------
__global__ void bg_copy_kernel(const float4* __restrict__ Kbg,
                               const float4* __restrict__ Vbg) {
    int i = blockIdx.x * blockDim.x + threadIdx.x;
    const int NBG4 = BH * Ll * (HD / 4);
    if (i >= NBG4) return;
    int bh  = i >> 14;
    int rem = i & 16383;
    int dst = bh * (LKV * HD / 4) + (Ll * HD / 4) + rem;
    float4 k = Kbg[i];
    float4 v = Vbg[i];
    k.x *= ALPHA; k.y *= ALPHA; k.z *= ALPHA; k.w *= ALPHA;
    v.x *= ALPHA; v.y *= ALPHA; v.z *= ALPHA; v.w *= ALPHA;
    ((float4*)g_K)[dst] = k;
    ((float4*)g_V)[dst] = v;
}

// ---------------------------------------------------------------------------
// tf32 GEMM v2: BM=128, BN=128, BK=16; 256 threads = 8 warps (2m x 4n),
// warp tile 64x32 = 4 m16 x 4 n8 tiles -> 32 MMAs per k0 step per warp.
// ---------------------------------------------------------------------------
#define PA 20    // As row stride (uint32): 16 k + pad
#define PB 136   // Bs row stride (uint32): 128 n + pad

// global->reg loaders (fp32)
__device__ __forceinline__ void g_load_A(float4* ra, const float* __restrict__ A,
                                         int m0, int k0, int t) {
    int row = t >> 1, cg = (t & 1) * 8;
    const float* p = A + (m0 + row) * Dd + k0 + cg;
    ra[0] = *(const float4*)p;
    ra[1] = *(const float4*)(p + 4);
}
__device__ __forceinline__ void g_load_B(float4* rb, const float* __restrict__ W,
                                         int n0, int k0, int t) {
    int row = t >> 4, c4 = (t & 15) * 4;
    const float* p = W + (k0 + row) * Dd + n0 + c4;
    rb[0] = *(const float4*)p;
    rb[1] = *(const float4*)(p + 64);
}
// reg->smem (cvt to tf32)
__device__ __forceinline__ void s_store_A(uint32_t* As, const float4* ra, int t) {
    int row = t >> 1, cg = (t & 1) * 8;
    uint32_t* p = As + row * PA + cg;
    p[0] = f2tf(ra[0].x); p[1] = f2tf(ra[0].y); p[2] = f2tf(ra[0].z); p[3] = f2tf(ra[0].w);
    p[4] = f2tf(ra[1].x); p[5] = f2tf(ra[1].y); p[6] = f2tf(ra[1].z); p[7] = f2tf(ra[1].w);
}
__device__ __forceinline__ void s_store_B(uint32_t* Bs, const float4* rb, int t) {
    int row = t >> 4, c4 = (t & 15) * 4;
    uint32_t* p = Bs + row * PB + c4;
    p[0]  = f2tf(rb[0].x); p[1]  = f2tf(rb[0].y); p[2]  = f2tf(rb[0].z); p[3]  = f2tf(rb[0].w);
    p[64] = f2tf(rb[1].x); p[65] = f2tf(rb[1].y); p[66] = f2tf(rb[1].z); p[67] = f2tf(rb[1].w);
}

__device__ __forceinline__ void compute_tile(float (*acc)[4][4],
                                             const uint32_t* __restrict__ As,
                                             const uint32_t* __restrict__ Bs, int t) {
    const int lane = t & 31, w = t >> 5;
    const int g = lane >> 2, tig = lane & 3;
    const int wm = (w >> 2) * 64, wn = (w & 3) * 32;
#pragma unroll
    for (int kk = 0; kk < 16; kk += 8) {
        uint32_t a[4][4], b[4][2];
#pragma unroll
        for (int mt = 0; mt < 4; mt++) {
            int r = wm + mt * 16 + g;
            a[mt][0] = As[r * PA + kk + tig];
            a[mt][1] = As[(r + 8) * PA + kk + tig];
            a[mt][2] = As[r * PA + kk + tig + 4];
            a[mt][3] = As[(r + 8) * PA + kk + tig + 4];
        }
#pragma unroll
        for (int nt = 0; nt < 4; nt++) {
            int c = wn + nt * 8 + g;
            b[nt][0] = Bs[(kk + tig) * PB + c];
            b[nt][1] = Bs[(kk + tig + 4) * PB + c];
        }
#pragma unroll
        for (int mt = 0; mt < 4; mt++)
#pragma unroll
            for (int nt = 0; nt < 4; nt++)
                mma_tf32(acc[mt][nt], a[mt], b[nt]);
    }
}

// ---------------------------------------------------------------------------
// 2) QKV projection GEMM (tensor cores), scatter to head layout
// ---------------------------------------------------------------------------
__global__ void __launch_bounds__(256) proj_kernel(const float* __restrict__ X,
                            const float* __restrict__ Wq,
                            const float* __restrict__ Wk,
                            const float* __restrict__ Wv) {
    __shared__ uint32_t As[2][128 * PA];
    __shared__ uint32_t Bs[2][16 * PB];

    const int m0 = blockIdx.y * 128;
    const int n0 = blockIdx.x * 128;
    const int z  = blockIdx.z;
    const float* __restrict__ W = (z == 0) ? Wq : ((z == 1) ? Wk : Wv);
    const int t = threadIdx.x;

    float acc[4][4][4];
#pragma unroll
    for (int mt = 0; mt < 4; mt++)
#pragma unroll
        for (int nt = 0; nt < 4; nt++)
#pragma unroll
            for (int i = 0; i < 4; i++) acc[mt][nt][i] = 0.0f;

    float4 ra[2], rb[2];
    g_load_A(ra, X, m0, 0, t);
    g_load_B(rb, W, n0, 0, t);
    s_store_A(As[0], ra, t);
    s_store_B(Bs[0], rb, t);
    __syncthreads();

    int cur = 0;
    for (int k0 = 16; k0 < Dd; k0 += 16) {
        g_load_A(ra, X, m0, k0, t);
        g_load_B(rb, W, n0, k0, t);
        compute_tile(acc, As[cur], Bs[cur], t);
        s_store_A(As[cur ^ 1], ra, t);
        s_store_B(Bs[cur ^ 1], rb, t);
        __syncthreads();
        cur ^= 1;
    }
    compute_tile(acc, As[cur], Bs[cur], t);

    // Epilogue: scatter to head-batched layout
    const int lane = t & 31, w = t >> 5;
    const int g = lane >> 2, tig = lane & 3;
    const int wm = (w >> 2) * 64, wn = (w & 3) * 32;
#pragma unroll
    for (int mt = 0; mt < 4; mt++) {
#pragma unroll
        for (int half = 0; half < 2; half++) {
            int m = m0 + wm + mt * 16 + g + half * 8;
            int b = m >> 10, l = m & 1023;
#pragma unroll
            for (int nt = 0; nt < 4; nt++) {
                int col = n0 + wn + nt * 8 + 2 * tig;
                int h = col >> 6, d = col & 63;
                float2 v = make_float2(acc[mt][nt][half * 2 + 0],
                                       acc[mt][nt][half * 2 + 1]);
                if (z == 0)
                    *(float2*)&g_Q[((b * Hh + h) * Ll + l) * HD + d] = v;
                else if (z == 1)
                    *(float2*)&g_K[((b * Hh + h) * LKV + l) * HD + d] = v;
                else
                    *(float2*)&g_V[((b * Hh + h) * LKV + l) * HD + d] = v;
            }
        }
    }
}

// ---------------------------------------------------------------------------
// 3) Flash attention on tensor cores (tf32; split-tf32 for QK^T) — unchanged
// ---------------------------------------------------------------------------
__global__ void __launch_bounds__(128) attn_kernel() {
    __shared__ uint32_t Khi[32][68];
    __shared__ uint32_t Klo[32][68];
    __shared__ uint32_t VTs[64][36];
    __shared__ uint32_t Ps [64][36];

    const int bh = blockIdx.y;
    const int q0 = blockIdx.x * 64;
    const int t = threadIdx.x;
    const int w = t >> 5, lane = t & 31;
    const int g = lane >> 2, tig = lane & 3;
    const int qw = w * 16;

    uint32_t qhi[8][4], qlo[8][4];
    {
        const float* Qp = g_Q + (bh * Ll + q0 + qw) * HD;
#pragma unroll
        for (int kk = 0; kk < 8; kk++) {
            int c0 = kk * 8 + tig;
            float x[4];
            x[0] = Qp[g * HD + c0] * SMSCALE;
            x[1] = Qp[(g + 8) * HD + c0] * SMSCALE;
            x[2] = Qp[g * HD + c0 + 4] * SMSCALE;
            x[3] = Qp[(g + 8) * HD + c0 + 4] * SMSCALE;
#pragma unroll
            for (int i = 0; i < 4; i++) {
                uint32_t hi = f2tf(x[i]);
                qhi[kk][i] = hi;
                qlo[kk][i] = f2tf(x[i] - __uint_as_float(hi));
            }
        }
    }

    float o[8][4];
#pragma unroll
    for (int nt = 0; nt < 8; nt++)
#pragma unroll
        for (int i = 0; i < 4; i++) o[nt][i] = 0.0f;
    float m0 = -INFINITY, m1 = -INFINITY, l0 = 0.0f, l1 = 0.0f;

    const float4* Kg = (const float4*)(g_K + (size_t)bh * LKV * HD);
    const float4* Vg = (const float4*)(g_V + (size_t)bh * LKV * HD);

    for (int kt = 0; kt < LKV / 32; kt++) {
        __syncthreads();
        int base4 = kt * 32 * 16;
#pragma unroll
        for (int u = 0; u < 4; u++) {
            int idx4 = u * 128 + t;
            int row = idx4 >> 4, c4 = idx4 & 15;
            float4 kx = Kg[base4 + idx4];
            float4 vx = Vg[base4 + idx4];
            float kv[4] = {kx.x, kx.y, kx.z, kx.w};
            float vv[4] = {vx.x, vx.y, vx.z, vx.w};
#pragma unroll
            for (int j = 0; j < 4; j++) {
                uint32_t hi = f2tf(kv[j]);
                Khi[row][c4 * 4 + j] = hi;
                Klo[row][c4 * 4 + j] = f2tf(kv[j] - __uint_as_float(hi));
                VTs[c4 * 4 + j][row] = f2tf(vv[j]);
            }
        }
        __syncthreads();

        float s[4][4];
#pragma unroll
        for (int nt = 0; nt < 4; nt++)
#pragma unroll
            for (int i = 0; i < 4; i++) s[nt][i] = 0.0f;
#pragma unroll
        for (int kk = 0; kk < 8; kk++) {
#pragma unroll
            for (int nt = 0; nt < 4; nt++) {
                int c = nt * 8 + g;
                uint32_t bhi[2] = {Khi[c][kk * 8 + tig], Khi[c][kk * 8 + tig + 4]};
                uint32_t blo[2] = {Klo[c][kk * 8 + tig], Klo[c][kk * 8 + tig + 4]};
                mma_tf32(s[nt], qlo[kk], bhi);
                mma_tf32(s[nt], qhi[kk], blo);
                mma_tf32(s[nt], qhi[kk], bhi);
            }
        }

        float mx0 = fmaxf(fmaxf(s[0][0], s[0][1]), fmaxf(s[1][0], s[1][1]));
        mx0 = fmaxf(mx0, fmaxf(fmaxf(s[2][0], s[2][1]), fmaxf(s[3][0], s[3][1])));
        float mx1 = fmaxf(fmaxf(s[0][2], s[0][3]), fmaxf(s[1][2], s[1][3]));
        mx1 = fmaxf(mx1, fmaxf(fmaxf(s[2][2], s[2][3]), fmaxf(s[3][2], s[3][3])));
#pragma unroll
        for (int off = 1; off < 4; off <<= 1) {
            mx0 = fmaxf(mx0, __shfl_xor_sync(0xffffffffu, mx0, off));
            mx1 = fmaxf(mx1, __shfl_xor_sync(0xffffffffu, mx1, off));
        }
        float mn0 = fmaxf(m0, mx0), mn1 = fmaxf(m1, mx1);
        float corr0 = __expf(m0 - mn0), corr1 = __expf(m1 - mn1);
        m0 = mn0; m1 = mn1;
        float rs0 = 0.0f, rs1 = 0.0f;
#pragma unroll
        for (int nt = 0; nt < 4; nt++) {
            float p00 = __expf(s[nt][0] - mn0);
            float p01 = __expf(s[nt][1] - mn0);
            float p10 = __expf(s[nt][2] - mn1);
            float p11 = __expf(s[nt][3] - mn1);
            rs0 += p00 + p01;
            rs1 += p10 + p11;
            int col = nt * 8 + 2 * tig;
            *(uint2*)&Ps[qw + g][col]     = make_uint2(f2tf(p00), f2tf(p01));
            *(uint2*)&Ps[qw + g + 8][col] = make_uint2(f2tf(p10), f2tf(p11));
        }
#pragma unroll
        for (int off = 1; off < 4; off <<= 1) {
            rs0 += __shfl_xor_sync(0xffffffffu, rs0, off);
            rs1 += __shfl_xor_sync(0xffffffffu, rs1, off);
        }
        l0 = l0 * corr0 + rs0;
        l1 = l1 * corr1 + rs1;
#pragma unroll
        for (int nt = 0; nt < 8; nt++) {
            o[nt][0] *= corr0; o[nt][1] *= corr0;
            o[nt][2] *= corr1; o[nt][3] *= corr1;
        }
        __syncwarp();

#pragma unroll
        for (int kk = 0; kk < 4; kk++) {
            uint32_t a[4] = {Ps[qw + g][kk * 8 + tig],
                             Ps[qw + g + 8][kk * 8 + tig],
                             Ps[qw + g][kk * 8 + tig + 4],
                             Ps[qw + g + 8][kk * 8 + tig + 4]};
#pragma unroll
            for (int nt = 0; nt < 8; nt++) {
                int c = nt * 8 + g;
                uint32_t b[2] = {VTs[c][kk * 8 + tig], VTs[c][kk * 8 + tig + 4]};
                mma_tf32(o[nt], a, b);
            }
        }
    }

    float inv0 = 1.0f / l0, inv1 = 1.0f / l1;
    const int h = bh % Hh, b = bh / Hh;
    int r0 = q0 + qw + g, r1 = r0 + 8;
#pragma unroll
    for (int nt = 0; nt < 8; nt++) {
        int col = h * HD + nt * 8 + 2 * tig;
        *(float2*)&g_Ctx[(b * Ll + r0) * Dd + col] =
            make_float2(o[nt][0] * inv0, o[nt][1] * inv0);
        *(float2*)&g_Ctx[(b * Ll + r1) * Dd + col] =
            make_float2(o[nt][2] * inv1, o[nt][3] * inv1);
    }
}

// ---------------------------------------------------------------------------
// 4) Output projection: out = Ctx @ Wo + bo  (tensor cores)
// ---------------------------------------------------------------------------
__global__ void __launch_bounds__(256) oproj_kernel(const float* __restrict__ Wo,
                             const float* __restrict__ bo,
                             float* __restrict__ out) {
    __shared__ uint32_t As[2][128 * PA];
    __shared__ uint32_t Bs[2][16 * PB];

    const int m0 = blockIdx.y * 128;
    const int n0 = blockIdx.x * 128;
    const int t = threadIdx.x;

    float acc[4][4][4];
#pragma unroll
    for (int mt = 0; mt < 4; mt++)
#pragma unroll
        for (int nt = 0; nt < 4; nt++)
#pragma unroll
            for (int i = 0; i < 4; i++) acc[mt][nt][i] = 0.0f;

    float4 ra[2], rb[2];
    g_load_A(ra, g_Ctx, m0, 0, t);
    g_load_B(rb, Wo, n0, 0, t);
    s_store_A(As[0], ra, t);
    s_store_B(Bs[0], rb, t);
    __syncthreads();

    int cur = 0;
    for (int k0 = 16; k0 < Dd; k0 += 16) {
        g_load_A(ra, g_Ctx, m0, k0, t);
        g_load_B(rb, Wo, n0, k0, t);
        compute_tile(acc, As[cur], Bs[cur], t);
        s_store_A(As[cur ^ 1], ra, t);
        s_store_B(Bs[cur ^ 1], rb, t);
        __syncthreads();
        cur ^= 1;
    }
    compute_tile(acc, As[cur], Bs[cur], t);

    const int lane = t & 31, w = t >> 5;
    const int g = lane >> 2, tig = lane & 3;
    const int wm = (w >> 2) * 64, wn = (w & 3) * 32;
#pragma unroll
    for (int mt = 0; mt < 4; mt++) {
#pragma unroll
        for (int half = 0; half < 2; half++) {
            int m = m0 + wm + mt * 16 + g + half * 8;
#pragma unroll
            for (int nt = 0; nt < 4; nt++) {
                int col = n0 + wn + nt * 8 + 2 * tig;
                float2 bias = *(const float2*)(bo + col);
                float2 v = make_float2(acc[mt][nt][half * 2 + 0] + bias.x,
                                       acc[mt][nt][half * 2 + 1] + bias.y);
                *(float2*)&out[m * Dd + col] = v;
            }
        }
    }
}

// ---------------------------------------------------------------------------
extern "C" void kernel_launch(void* const* d_in, const int* in_sizes, int n_in,
                              void* d_out, int out_size) {
    const float* X   = (const float*)d_in[0];
    const float* Kbg = (const float*)d_in[1];
    const float* Vbg = (const float*)d_in[2];
    const float* Wq  = (const float*)d_in[3];
    const float* Wk  = (const float*)d_in[4];
    const float* Wv  = (const float*)d_in[5];
    const float* Wo  = (const float*)d_in[6];
    const float* bo  = (const float*)d_in[7];
    float* out = (float*)d_out;

    bg_copy_kernel<<<5120, 256>>>((const float4*)Kbg, (const float4*)Vbg);
    proj_kernel<<<dim3(10, 32, 3), 256>>>(X, Wq, Wk, Wv);
    attn_kernel<<<dim3(16, 80), 128>>>();
    oproj_kernel<<<dim3(10, 32), 256>>>(Wo, bo, out);
}

// round 7
// speedup vs baseline: 2.2428x; 1.0294x over previous
#include <cuda_runtime.h>
#include <math.h>
#include <stdint.h>

// Problem constants
#define Bb   4
#define Ll   1024
#define Dd   1280
#define Hh   20
#define HD   64
#define BH   (Bb*Hh)        // 80
#define LKV  (2*Ll)         // 2048
#define Mm   (Bb*Ll)        // 4096
#define ALPHA 0.48f
#define SMSCALE 0.125f      // 1/sqrt(64)

// Persistent scratch (device globals; no allocation allowed)
__device__ float g_Q[BH * Ll * HD];          // [bh][q][d]
__device__ float g_K[BH * LKV * HD];         // [bh][kv][d]
__device__ float g_V[BH * LKV * HD];         // [bh][kv][d]
__device__ float g_Ctx[Mm * Dd];             // [b*L + l][h*64 + d], tf32-rounded
__device__ float g_Xt[Mm * Dd];              // X pre-rounded to tf32
__device__ float g_Wt[4 * Dd * Dd];          // Wq,Wk,Wv,Wo pre-rounded to tf32

// ---------------------------------------------------------------------------
// tf32 helpers
// ---------------------------------------------------------------------------
__device__ __forceinline__ uint32_t f2tf(float f) {
    uint32_t r;
    asm("cvt.rna.tf32.f32 %0, %1;" : "=r"(r) : "f"(f));
    return r;
}

__device__ __forceinline__ uint4 f2tf4(float4 v) {
    return make_uint4(f2tf(v.x), f2tf(v.y), f2tf(v.z), f2tf(v.w));
}

__device__ __forceinline__ void mma_tf32(float* c, const uint32_t* a, const uint32_t* b) {
    asm volatile(
        "mma.sync.aligned.m16n8k8.row.col.f32.tf32.tf32.f32 "
        "{%0,%1,%2,%3}, {%4,%5,%6,%7}, {%8,%9}, {%0,%1,%2,%3};"
        : "+f"(c[0]), "+f"(c[1]), "+f"(c[2]), "+f"(c[3])
        : "r"(a[0]), "r"(a[1]), "r"(a[2]), "r"(a[3]), "r"(b[0]), "r"(b[1]));
}

__device__ __forceinline__ void cp16(uint32_t s, const void* g) {
    asm volatile("cp.async.cg.shared.global [%0], [%1], 16;\n" :: "r"(s), "l"(g));
}
__device__ __forceinline__ void cp_commit() {
    asm volatile("cp.async.commit_group;\n");
}
__device__ __forceinline__ void cp_wait2() {
    asm volatile("cp.async.wait_group 2;\n");
}

// ---------------------------------------------------------------------------
// 0) Prepass: round X and weights to tf32 once
// ---------------------------------------------------------------------------
__global__ void cvt_prepass(const float4* __restrict__ X,
                            const float4* __restrict__ Wq,
                            const float4* __restrict__ Wk,
                            const float4* __restrict__ Wv,
                            const float4* __restrict__ Wo) {
    int i = blockIdx.x * blockDim.x + threadIdx.x;
    const int NX4 = Mm * Dd / 4;        // 1,310,720
    const int NW4 = Dd * Dd / 4;        //   409,600
    if (i < NX4) ((uint4*)g_Xt)[i] = f2tf4(X[i]);
    if (i < NW4) {
        ((uint4*)g_Wt)[i]           = f2tf4(Wq[i]);
        ((uint4*)g_Wt)[NW4 + i]     = f2tf4(Wk[i]);
        ((uint4*)g_Wt)[2 * NW4 + i] = f2tf4(Wv[i]);
        ((uint4*)g_Wt)[3 * NW4 + i] = f2tf4(Wo[i]);
    }
}

// ---------------------------------------------------------------------------
// 1) Scale-copy the context-bank KV into the back half of g_K / g_V
// ---------------------------------------------------------------------------
__global__ void bg_copy_kernel(const float4* __restrict__ Kbg,
                               const float4* __restrict__ Vbg) {
    int i = blockIdx.x * blockDim.x + threadIdx.x;
    const int NBG4 = BH * Ll * (HD / 4);
    if (i >= NBG4) return;
    int bh  = i >> 14;
    int rem = i & 16383;
    int dst = bh * (LKV * HD / 4) + (Ll * HD / 4) + rem;
    float4 k = Kbg[i];
    float4 v = Vbg[i];
    k.x *= ALPHA; k.y *= ALPHA; k.z *= ALPHA; k.w *= ALPHA;
    v.x *= ALPHA; v.y *= ALPHA; v.z *= ALPHA; v.w *= ALPHA;
    ((float4*)g_K)[dst] = k;
    ((float4*)g_V)[dst] = v;
}

// ---------------------------------------------------------------------------
// tf32 GEMM v3: BM=128, BN=128, BK=16; 256 threads = 8 warps (2m x 4n),
// cp.async 4-stage pipeline, inputs pre-rounded to tf32 (no cvt in loop).
// ---------------------------------------------------------------------------
#define PA 20      // As row stride (uint32): 16 k + pad
#define PB 136     // Bs row stride (uint32): 128 n + pad
#define NSTAGE 4
#define A_STG (128 * PA)
#define B_STG (16 * PB)
#define SMEM_BYTES (NSTAGE * (A_STG + B_STG) * 4)   // 75,776 B

__device__ __forceinline__ void stage_load(uint32_t sA, uint32_t sB,
                                           const float* __restrict__ A,
                                           const float* __restrict__ W,
                                           int m0, int n0, int k0, int t) {
    int arow = t >> 1, acg = (t & 1) * 8;
    const float* ap = A + (m0 + arow) * Dd + k0 + acg;
    cp16(sA + (arow * PA + acg) * 4, ap);
    cp16(sA + (arow * PA + acg + 4) * 4, ap + 4);
    int brow = t >> 4, bc4 = (t & 15) * 4;
    const float* bp = W + (k0 + brow) * Dd + n0 + bc4;
    cp16(sB + (brow * PB + bc4) * 4, bp);
    cp16(sB + (brow * PB + bc4 + 64) * 4, bp + 64);
    cp_commit();
}

__device__ __forceinline__ void compute_tile(float (*acc)[4][4],
                                             const uint32_t* __restrict__ As,
                                             const uint32_t* __restrict__ Bs, int t) {
    const int lane = t & 31, w = t >> 5;
    const int g = lane >> 2, tig = lane & 3;
    const int wm = (w >> 2) * 64, wn = (w & 3) * 32;
#pragma unroll
    for (int kk = 0; kk < 16; kk += 8) {
        uint32_t a[4][4], b[4][2];
#pragma unroll
        for (int mt = 0; mt < 4; mt++) {
            int r = wm + mt * 16 + g;
            a[mt][0] = As[r * PA + kk + tig];
            a[mt][1] = As[(r + 8) * PA + kk + tig];
            a[mt][2] = As[r * PA + kk + tig + 4];
            a[mt][3] = As[(r + 8) * PA + kk + tig + 4];
        }
#pragma unroll
        for (int nt = 0; nt < 4; nt++) {
            int c = wn + nt * 8 + g;
            b[nt][0] = Bs[(kk + tig) * PB + c];
            b[nt][1] = Bs[(kk + tig + 4) * PB + c];
        }
#pragma unroll
        for (int mt = 0; mt < 4; mt++)
#pragma unroll
            for (int nt = 0; nt < 4; nt++)
                mma_tf32(acc[mt][nt], a[mt], b[nt]);
    }
}

// Shared mainloop: returns with acc filled
__device__ __forceinline__ void gemm_mainloop(float (*acc)[4][4],
                                              const float* __restrict__ A,
                                              const float* __restrict__ W,
                                              int m0, int n0, int t,
                                              uint32_t* smem) {
    uint32_t sbase = (uint32_t)__cvta_generic_to_shared(smem);
    const uint32_t aB = sbase, bB = sbase + NSTAGE * A_STG * 4;
    const int KT = Dd / 16;   // 80

#pragma unroll
    for (int s = 0; s < NSTAGE - 1; s++)
        stage_load(aB + s * A_STG * 4, bB + s * B_STG * 4, A, W, m0, n0, s * 16, t);

    for (int kt = 0; kt < KT; kt++) {
        cp_wait2();
        __syncthreads();
        int nxt = kt + NSTAGE - 1;
        if (nxt < KT) {
            int sl = nxt & (NSTAGE - 1);
            stage_load(aB + sl * A_STG * 4, bB + sl * B_STG * 4, A, W, m0, n0, nxt * 16, t);
        } else {
            cp_commit();   // empty group keeps wait_group accounting aligned
        }
        int cur = kt & (NSTAGE - 1);
        compute_tile(acc, smem + cur * A_STG, smem + NSTAGE * A_STG + cur * B_STG, t);
    }
}

// ---------------------------------------------------------------------------
// 2) QKV projection GEMM, scatter to head layout
// ---------------------------------------------------------------------------
__global__ void __launch_bounds__(256) proj_kernel() {
    extern __shared__ uint32_t smem[];
    const int m0 = blockIdx.y * 128;
    const int n0 = blockIdx.x * 128;
    const int z  = blockIdx.z;
    const int t  = threadIdx.x;

    float acc[4][4][4];
#pragma unroll
    for (int mt = 0; mt < 4; mt++)
#pragma unroll
        for (int nt = 0; nt < 4; nt++)
#pragma unroll
            for (int i = 0; i < 4; i++) acc[mt][nt][i] = 0.0f;

    gemm_mainloop(acc, g_Xt, g_Wt + z * Dd * Dd, m0, n0, t, smem);

    const int lane = t & 31, w = t >> 5;
    const int g = lane >> 2, tig = lane & 3;
    const int wm = (w >> 2) * 64, wn = (w & 3) * 32;
#pragma unroll
    for (int mt = 0; mt < 4; mt++) {
#pragma unroll
        for (int half = 0; half < 2; half++) {
            int m = m0 + wm + mt * 16 + g + half * 8;
            int b = m >> 10, l = m & 1023;
#pragma unroll
            for (int nt = 0; nt < 4; nt++) {
                int col = n0 + wn + nt * 8 + 2 * tig;
                int h = col >> 6, d = col & 63;
                float2 v = make_float2(acc[mt][nt][half * 2 + 0],
                                       acc[mt][nt][half * 2 + 1]);
                if (z == 0)
                    *(float2*)&g_Q[((b * Hh + h) * Ll + l) * HD + d] = v;
                else if (z == 1)
                    *(float2*)&g_K[((b * Hh + h) * LKV + l) * HD + d] = v;
                else
                    *(float2*)&g_V[((b * Hh + h) * LKV + l) * HD + d] = v;
            }
        }
    }
}

// ---------------------------------------------------------------------------
// 3) Flash attention on tensor cores (tf32; split-tf32 for QK^T)
//    Output written pre-rounded to tf32 (oproj A operand needs no cvt).
// ---------------------------------------------------------------------------
__global__ void __launch_bounds__(128) attn_kernel() {
    __shared__ uint32_t Khi[32][68];
    __shared__ uint32_t Klo[32][68];
    __shared__ uint32_t VTs[64][36];
    __shared__ uint32_t Ps [64][36];

    const int bh = blockIdx.y;
    const int q0 = blockIdx.x * 64;
    const int t = threadIdx.x;
    const int w = t >> 5, lane = t & 31;
    const int g = lane >> 2, tig = lane & 3;
    const int qw = w * 16;

    uint32_t qhi[8][4], qlo[8][4];
    {
        const float* Qp = g_Q + (bh * Ll + q0 + qw) * HD;
#pragma unroll
        for (int kk = 0; kk < 8; kk++) {
            int c0 = kk * 8 + tig;
            float x[4];
            x[0] = Qp[g * HD + c0] * SMSCALE;
            x[1] = Qp[(g + 8) * HD + c0] * SMSCALE;
            x[2] = Qp[g * HD + c0 + 4] * SMSCALE;
            x[3] = Qp[(g + 8) * HD + c0 + 4] * SMSCALE;
#pragma unroll
            for (int i = 0; i < 4; i++) {
                uint32_t hi = f2tf(x[i]);
                qhi[kk][i] = hi;
                qlo[kk][i] = f2tf(x[i] - __uint_as_float(hi));
            }
        }
    }

    float o[8][4];
#pragma unroll
    for (int nt = 0; nt < 8; nt++)
#pragma unroll
        for (int i = 0; i < 4; i++) o[nt][i] = 0.0f;
    float m0 = -INFINITY, m1 = -INFINITY, l0 = 0.0f, l1 = 0.0f;

    const float4* Kg = (const float4*)(g_K + (size_t)bh * LKV * HD);
    const float4* Vg = (const float4*)(g_V + (size_t)bh * LKV * HD);

    for (int kt = 0; kt < LKV / 32; kt++) {
        __syncthreads();
        int base4 = kt * 32 * 16;
#pragma unroll
        for (int u = 0; u < 4; u++) {
            int idx4 = u * 128 + t;
            int row = idx4 >> 4, c4 = idx4 & 15;
            float4 kx = Kg[base4 + idx4];
            float4 vx = Vg[base4 + idx4];
            float kv[4] = {kx.x, kx.y, kx.z, kx.w};
            float vv[4] = {vx.x, vx.y, vx.z, vx.w};
#pragma unroll
            for (int j = 0; j < 4; j++) {
                uint32_t hi = f2tf(kv[j]);
                Khi[row][c4 * 4 + j] = hi;
                Klo[row][c4 * 4 + j] = f2tf(kv[j] - __uint_as_float(hi));
                VTs[c4 * 4 + j][row] = f2tf(vv[j]);
            }
        }
        __syncthreads();

        float s[4][4];
#pragma unroll
        for (int nt = 0; nt < 4; nt++)
#pragma unroll
            for (int i = 0; i < 4; i++) s[nt][i] = 0.0f;
#pragma unroll
        for (int kk = 0; kk < 8; kk++) {
#pragma unroll
            for (int nt = 0; nt < 4; nt++) {
                int c = nt * 8 + g;
                uint32_t bhi[2] = {Khi[c][kk * 8 + tig], Khi[c][kk * 8 + tig + 4]};
                uint32_t blo[2] = {Klo[c][kk * 8 + tig], Klo[c][kk * 8 + tig + 4]};
                mma_tf32(s[nt], qlo[kk], bhi);
                mma_tf32(s[nt], qhi[kk], blo);
                mma_tf32(s[nt], qhi[kk], bhi);
            }
        }

        float mx0 = fmaxf(fmaxf(s[0][0], s[0][1]), fmaxf(s[1][0], s[1][1]));
        mx0 = fmaxf(mx0, fmaxf(fmaxf(s[2][0], s[2][1]), fmaxf(s[3][0], s[3][1])));
        float mx1 = fmaxf(fmaxf(s[0][2], s[0][3]), fmaxf(s[1][2], s[1][3]));
        mx1 = fmaxf(mx1, fmaxf(fmaxf(s[2][2], s[2][3]), fmaxf(s[3][2], s[3][3])));
#pragma unroll
        for (int off = 1; off < 4; off <<= 1) {
            mx0 = fmaxf(mx0, __shfl_xor_sync(0xffffffffu, mx0, off));
            mx1 = fmaxf(mx1, __shfl_xor_sync(0xffffffffu, mx1, off));
        }
        float mn0 = fmaxf(m0, mx0), mn1 = fmaxf(m1, mx1);
        float corr0 = __expf(m0 - mn0), corr1 = __expf(m1 - mn1);
        m0 = mn0; m1 = mn1;
        float rs0 = 0.0f, rs1 = 0.0f;
#pragma unroll
        for (int nt = 0; nt < 4; nt++) {
            float p00 = __expf(s[nt][0] - mn0);
            float p01 = __expf(s[nt][1] - mn0);
            float p10 = __expf(s[nt][2] - mn1);
            float p11 = __expf(s[nt][3] - mn1);
            rs0 += p00 + p01;
            rs1 += p10 + p11;
            int col = nt * 8 + 2 * tig;
            *(uint2*)&Ps[qw + g][col]     = make_uint2(f2tf(p00), f2tf(p01));
            *(uint2*)&Ps[qw + g + 8][col] = make_uint2(f2tf(p10), f2tf(p11));
        }
#pragma unroll
        for (int off = 1; off < 4; off <<= 1) {
            rs0 += __shfl_xor_sync(0xffffffffu, rs0, off);
            rs1 += __shfl_xor_sync(0xffffffffu, rs1, off);
        }
        l0 = l0 * corr0 + rs0;
        l1 = l1 * corr1 + rs1;
#pragma unroll
        for (int nt = 0; nt < 8; nt++) {
            o[nt][0] *= corr0; o[nt][1] *= corr0;
            o[nt][2] *= corr1; o[nt][3] *= corr1;
        }
        __syncwarp();

#pragma unroll
        for (int kk = 0; kk < 4; kk++) {
            uint32_t a[4] = {Ps[qw + g][kk * 8 + tig],
                             Ps[qw + g + 8][kk * 8 + tig],
                             Ps[qw + g][kk * 8 + tig + 4],
                             Ps[qw + g + 8][kk * 8 + tig + 4]};
#pragma unroll
            for (int nt = 0; nt < 8; nt++) {
                int c = nt * 8 + g;
                uint32_t b[2] = {VTs[c][kk * 8 + tig], VTs[c][kk * 8 + tig + 4]};
                mma_tf32(o[nt], a, b);
            }
        }
    }

    float inv0 = 1.0f / l0, inv1 = 1.0f / l1;
    const int h = bh % Hh, b = bh / Hh;
    int r0 = q0 + qw + g, r1 = r0 + 8;
#pragma unroll
    for (int nt = 0; nt < 8; nt++) {
        int col = h * HD + nt * 8 + 2 * tig;
        uint2 v0 = make_uint2(f2tf(o[nt][0] * inv0), f2tf(o[nt][1] * inv0));
        uint2 v1 = make_uint2(f2tf(o[nt][2] * inv1), f2tf(o[nt][3] * inv1));
        *(uint2*)&g_Ctx[(b * Ll + r0) * Dd + col] = v0;
        *(uint2*)&g_Ctx[(b * Ll + r1) * Dd + col] = v1;
    }
}

// ---------------------------------------------------------------------------
// 4) Output projection: out = Ctx @ Wo + bo
// ---------------------------------------------------------------------------
__global__ void __launch_bounds__(256) oproj_kernel(const float* __restrict__ bo,
                                                    float* __restrict__ out) {
    extern __shared__ uint32_t smem[];
    const int m0 = blockIdx.y * 128;
    const int n0 = blockIdx.x * 128;
    const int t = threadIdx.x;

    float acc[4][4][4];
#pragma unroll
    for (int mt = 0; mt < 4; mt++)
#pragma unroll
        for (int nt = 0; nt < 4; nt++)
#pragma unroll
            for (int i = 0; i < 4; i++) acc[mt][nt][i] = 0.0f;

    gemm_mainloop(acc, g_Ctx, g_Wt + 3 * Dd * Dd, m0, n0, t, smem);

    const int lane = t & 31, w = t >> 5;
    const int g = lane >> 2, tig = lane & 3;
    const int wm = (w >> 2) * 64, wn = (w & 3) * 32;
#pragma unroll
    for (int mt = 0; mt < 4; mt++) {
#pragma unroll
        for (int half = 0; half < 2; half++) {
            int m = m0 + wm + mt * 16 + g + half * 8;
#pragma unroll
            for (int nt = 0; nt < 4; nt++) {
                int col = n0 + wn + nt * 8 + 2 * tig;
                float2 bias = *(const float2*)(bo + col);
                float2 v = make_float2(acc[mt][nt][half * 2 + 0] + bias.x,
                                       acc[mt][nt][half * 2 + 1] + bias.y);
                *(float2*)&out[m * Dd + col] = v;
            }
        }
    }
}

// ---------------------------------------------------------------------------
extern "C" void kernel_launch(void* const* d_in, const int* in_sizes, int n_in,
                              void* d_out, int out_size) {
    const float* X   = (const float*)d_in[0];
    const float* Kbg = (const float*)d_in[1];
    const float* Vbg = (const float*)d_in[2];
    const float* Wq  = (const float*)d_in[3];
    const float* Wk  = (const float*)d_in[4];
    const float* Wv  = (const float*)d_in[5];
    const float* Wo  = (const float*)d_in[6];
    const float* bo  = (const float*)d_in[7];
    float* out = (float*)d_out;

    // Unconditional on every call (no static guards — harness rule).
    // Not a stream operation: safe under graph capture, idempotent.
    cudaFuncSetAttribute(proj_kernel,
                         cudaFuncAttributeMaxDynamicSharedMemorySize, SMEM_BYTES);
    cudaFuncSetAttribute(oproj_kernel,
                         cudaFuncAttributeMaxDynamicSharedMemorySize, SMEM_BYTES);

    cvt_prepass<<<5120, 256>>>((const float4*)X, (const float4*)Wq,
                               (const float4*)Wk, (const float4*)Wv,
                               (const float4*)Wo);
    bg_copy_kernel<<<5120, 256>>>((const float4*)Kbg, (const float4*)Vbg);
    proj_kernel<<<dim3(10, 32, 3), 256, SMEM_BYTES>>>();
    attn_kernel<<<dim3(16, 80), 128>>>();
    oproj_kernel<<<dim3(10, 32), 256, SMEM_BYTES>>>(bo, out);
}